// round 12
// baseline (speedup 1.0000x reference)
#include <cuda_runtime.h>
#include <cuda_bf16.h>
#include <cstdint>

#define B 4096
#define D 128
#define TEMP 100.0f
#define NT 512
#define NBLK 16                        // 256-row blocks
#define NTILES (NBLK * (NBLK + 1) / 2) // 136
#define BS (B * 64)                    // elems per plane
#define PLANE (BS * 2)                 // bytes per plane (512 KB)

// smem map (R7 layout)
#define SM_A     0
#define SM_B     65536
#define SM_META  98304
#define SM_RED   102400
#define SM_MB    110592                // mbarA, mbarB0, mbarB1, flag word
#define SMEM_SZ  110720

__device__ __align__(1024) __nv_bfloat16 g_xs[2 * BS];
__device__ __align__(16) float g_sq[B];
__device__ int   g_lab[B];
__device__ float g_pd[NBLK][B];
__device__ float g_pn[NBLK][B];
__device__ unsigned int g_sync1;       // phase-0 barrier; self-reset
__device__ unsigned int g_cnt2;        // fin ticket;      self-reset

__device__ __forceinline__ uint32_t smem_to_u32(const void* p) {
    uint32_t a;
    asm("{ .reg .u64 t; cvta.to.shared.u64 t, %1; cvt.u32.u64 %0, t; }"
        : "=r"(a) : "l"(p));
    return a;
}
__device__ __forceinline__ uint32_t swz(uint32_t x) { return x ^ ((x >> 3) & 0x70); }

#define MBAR_INIT(m, c) \
    asm volatile("mbarrier.init.shared.b64 [%0], %1;" \
                 :: "r"((uint32_t)(m)), "r"((uint32_t)(c)) : "memory")
#define MBAR_EXPECT(m, n) \
    asm volatile("mbarrier.arrive.expect_tx.shared.b64 _, [%0], %1;" \
                 :: "r"((uint32_t)(m)), "r"((uint32_t)(n)) : "memory")
#define MBAR_WAIT(m, par) do { \
    uint32_t _m = (uint32_t)(m); uint32_t _p = (uint32_t)(par); uint32_t _d; \
    asm volatile("{\n\t.reg .pred p;\n\t" \
        "mbarrier.try_wait.parity.acquire.cta.shared::cta.b64 p, [%1], %2;\n\t" \
        "selp.b32 %0, 1, 0, p;\n\t}" : "=r"(_d) : "r"(_m), "r"(_p) : "memory"); \
    if (!_d) { \
        asm volatile("{\n\t.reg .pred P1;\n\t" \
            "WL_%=:\n\t" \
            "mbarrier.try_wait.parity.acquire.cta.shared::cta.b64 P1, [%0], %1, 0x989680;\n\t" \
            "@P1 bra.uni WD_%=;\n\tbra.uni WL_%=;\n\tWD_%=:\n\t}" \
            :: "r"(_m), "r"(_p) : "memory"); \
    } } while (0)

__device__ __forceinline__ void bulk_cp(uint32_t dst, const void* src,
                                        uint32_t bytes, uint32_t mbar) {
    asm volatile(
        "cp.async.bulk.shared::cluster.global.mbarrier::complete_tx::bytes "
        "[%0], [%1], %2, [%3];"
        :: "r"(dst), "l"(src), "r"(bytes), "r"(mbar) : "memory");
}

#define LDSM_X4(r0, r1, r2, r3, addr) \
    asm volatile("ldmatrix.sync.aligned.m8n8.x4.shared.b16 {%0,%1,%2,%3}, [%4];" \
                 : "=r"(r0), "=r"(r1), "=r"(r2), "=r"(r3) : "r"(addr))
#define MMA16816(c, a, b0, b1) \
    asm volatile("mma.sync.aligned.m16n8k16.row.col.f32.bf16.bf16.f32 " \
                 "{%0,%1,%2,%3}, {%4,%5,%6,%7}, {%8,%9}, {%0,%1,%2,%3};" \
                 : "+f"((c)[0]), "+f"((c)[1]), "+f"((c)[2]), "+f"((c)[3]) \
                 : "r"((a)[0]), "r"((a)[1]), "r"((a)[2]), "r"((a)[3]), \
                   "r"(b0), "r"(b1))

// One K=128 MMA pass over a 32x32 warp tile. (R7 verbatim)
__device__ __forceinline__ void mma_pass(float acc[2][4][4],
                                         uint32_t abase, uint32_t bbase,
                                         uint32_t bstride,
                                         uint32_t pa, uint32_t pb) {
    #pragma unroll
    for (int ks = 0; ks < 8; ks++) {
        const uint32_t koff = (ks & 3) * 32;
        const uint32_t ka = abase + (ks >> 2) * 32768;
        const uint32_t kb = bbase + (ks >> 2) * bstride;
        uint32_t a0[4], a1[4], b0[4], b1[4];
        LDSM_X4(a0[0], a0[1], a0[2], a0[3], ka + swz(pa + koff));
        LDSM_X4(a1[0], a1[1], a1[2], a1[3], ka + swz(pa + 2048 + koff));
        LDSM_X4(b0[0], b0[1], b0[2], b0[3], kb + swz(pb + koff));
        LDSM_X4(b1[0], b1[1], b1[2], b1[3], kb + swz(pb + 2048 + koff));
        MMA16816(acc[0][0], a0, b0[0], b0[1]);
        MMA16816(acc[0][1], a0, b0[2], b0[3]);
        MMA16816(acc[0][2], a0, b1[0], b1[1]);
        MMA16816(acc[0][3], a0, b1[2], b1[3]);
        MMA16816(acc[1][0], a1, b0[0], b0[1]);
        MMA16816(acc[1][1], a1, b0[2], b0[3]);
        MMA16816(acc[1][2], a1, b1[0], b1[1]);
        MMA16816(acc[1][3], a1, b1[2], b1[3]);
    }
}

// ---------------------------------------------------------------------------
// Single kernel: phase 0 cooperative convert -> grid sync -> R7 main -> fin.
// ---------------------------------------------------------------------------
__global__ void __launch_bounds__(NT, 1)
snn_all(const float* __restrict__ x, const int* __restrict__ y,
        float* __restrict__ out) {
    extern __shared__ char smem[];
    uint32_t sb = smem_to_u32(smem);
    const int tid = threadIdx.x;
    const int lane = tid & 31;
    const int w = tid >> 5, wr = w >> 1, wc = w & 1;
    const int grp = lane >> 3, l7 = lane & 7;
    const float NEGC = -1.4426950408889634f / TEMP;

    int t = blockIdx.x, bi = 0;
    while (t >= NBLK - bi) { t -= NBLK - bi; bi++; }
    const int bj = bi + t;
    const bool diag = (bi == bj);
    const int row0 = bi * 256, col0 = bj * 256;

    const uint32_t mbA  = sb + SM_MB;
    const uint32_t mbB0 = sb + SM_MB + 8;
    const uint32_t mbB1 = sb + SM_MB + 16;
    if (tid == 0) { MBAR_INIT(mbA, 1); MBAR_INIT(mbB0, 1); MBAR_INIT(mbB1, 1); }

    // ---------------- phase 0: cooperative bf16 convert (CTAs 0..127) -------
    if (blockIdx.x < 128) {
        const int r = tid >> 4, g = tid & 15;      // 32 rows x 16 groups
        const int row = blockIdx.x * 32 + r;
        const float* xs = x + (size_t)row * D + g * 8;
        float4 v0 = reinterpret_cast<const float4*>(xs)[0];
        float4 v1 = reinterpret_cast<const float4*>(xs)[1];
        float s = v0.x * v0.x + v0.y * v0.y + v0.z * v0.z + v0.w * v0.w
                + v1.x * v1.x + v1.y * v1.y + v1.z * v1.z + v1.w * v1.w;
        #pragma unroll
        for (int o = 8; o; o >>= 1) s += __shfl_xor_sync(0xFFFFFFFFu, s, o);
        uint4 pk;
        asm("cvt.rn.bf16x2.f32 %0, %2, %1;" : "=r"(pk.x) : "f"(v0.x), "f"(v0.y));
        asm("cvt.rn.bf16x2.f32 %0, %2, %1;" : "=r"(pk.y) : "f"(v0.z), "f"(v0.w));
        asm("cvt.rn.bf16x2.f32 %0, %2, %1;" : "=r"(pk.z) : "f"(v1.x), "f"(v1.y));
        asm("cvt.rn.bf16x2.f32 %0, %2, %1;" : "=r"(pk.w) : "f"(v1.z), "f"(v1.w));
        char* dst = reinterpret_cast<char*>(g_xs) + (size_t)(g >> 3) * PLANE
                    + swz((uint32_t)row * 128 + (g & 7) * 16);
        *reinterpret_cast<uint4*>(dst) = pk;
        if (g == 0) { g_sq[row] = s; g_lab[row] = y[row]; }
    }

    // ---------------- grid-wide sync (all 136 CTAs co-resident) -------------
    __threadfence();
    asm volatile("fence.proxy.async;" ::: "memory");
    __syncthreads();
    if (tid == 0) {
        atomicAdd(&g_sync1, 1u);
        unsigned v;
        do {
            asm volatile("ld.acquire.gpu.u32 %0, [%1];"
                         : "=r"(v) : "l"(&g_sync1) : "memory");
        } while (v < (unsigned)NTILES);
    }
    __syncthreads();

    // ---------------- phase 1: R7 main (verbatim) ----------------------------
    const char* gx = reinterpret_cast<const char*>(g_xs);
    if (tid == 0) {
        MBAR_EXPECT(mbA, 65536);
        #pragma unroll
        for (int s = 0; s < 2; s++)
            bulk_cp(sb + SM_A + s * 32768,
                    gx + (size_t)s * PLANE + (size_t)row0 * 128, 32768, mbA);
        if (!diag) {
            MBAR_EXPECT(mbB0, 16384);
            #pragma unroll
            for (int s = 0; s < 2; s++)
                bulk_cp(sb + SM_B + s * 8192,
                        gx + (size_t)s * PLANE + (size_t)col0 * 128, 8192, mbB0);
        }
    }

    float* sqr  = reinterpret_cast<float*>(smem + SM_META);
    float* sqc  = sqr + 256;
    int*   labr = reinterpret_cast<int*>(sqc + 256);
    int*   labc = labr + 256;
    {
        int i = tid;
        if (i < 256) { sqr[i] = g_sq[row0 + i];  labr[i] = g_lab[row0 + i]; }
        else         { sqc[i - 256] = g_sq[col0 + i - 256];
                       labc[i - 256] = g_lab[col0 + i - 256]; }
    }
    __syncthreads();

    const uint32_t pa = (uint32_t)((wr * 32 + (grp & 1) * 8 + l7) * 128 + (grp >> 1) * 16);
    const uint32_t pb = (uint32_t)((wc * 32 + (grp >> 1) * 8 + l7) * 128 + (grp & 1) * 16);
    const int rbase = lane >> 2, cpair = (lane & 3) * 2;

    float sqi[4]; int labi[4];
    #pragma unroll
    for (int i = 0; i < 4; i++) {
        int rloc = wr * 32 + (i >> 1) * 16 + (i & 1) * 8 + rbase;
        sqi[i] = sqr[rloc];  labi[i] = labr[rloc];
    }
    float rs_d[4] = {0.f, 0.f, 0.f, 0.f}, rs_n[4] = {0.f, 0.f, 0.f, 0.f};

    float* rowD = reinterpret_cast<float*>(smem + SM_RED);
    float* rowN = rowD + 512;
    float* colD = rowN + 512;
    float* colN = colD + 512;

    MBAR_WAIT(mbA, 0);

    for (int c = 0; c < 4; c++) {
        if (!diag) {
            if (tid == 0 && c < 3) {
                uint32_t mb = (c & 1) ? mbB0 : mbB1;
                MBAR_EXPECT(mb, 16384);
                #pragma unroll
                for (int s = 0; s < 2; s++)
                    bulk_cp(sb + SM_B + (uint32_t)(((c + 1) & 1) * 16384 + s * 8192),
                            gx + (size_t)s * PLANE
                               + (size_t)(col0 + (c + 1) * 64) * 128, 8192, mb);
            }
            MBAR_WAIT((c & 1) ? mbB1 : mbB0, (c >> 1) & 1);
        }

        float acc[2][4][4];
        #pragma unroll
        for (int mt = 0; mt < 2; mt++)
            #pragma unroll
            for (int nt = 0; nt < 4; nt++)
                #pragma unroll
                for (int e = 0; e < 4; e++) acc[mt][nt][e] = 0.f;

        uint32_t bH, bstr;
        if (diag) { bH = sb + SM_A + c * 8192;  bstr = 32768; }
        else      { bH = sb + SM_B + (uint32_t)((c & 1) * 16384);  bstr = 8192; }
        mma_pass(acc, sb + SM_A, bH, bstr, pa, pb);

        float sqjt[8]; int labjt[8];
        #pragma unroll
        for (int k = 0; k < 8; k++) {
            int cloc = c * 64 + wc * 32 + (k >> 1) * 8 + cpair + (k & 1);
            sqjt[k] = diag ? sqr[cloc] : sqc[cloc];
            labjt[k] = diag ? labr[cloc] : labc[cloc];
        }
        float cs_d[8] = {0,0,0,0,0,0,0,0}, cs_n[8] = {0,0,0,0,0,0,0,0};

        #pragma unroll
        for (int mt = 0; mt < 2; mt++)
            #pragma unroll
            for (int nt = 0; nt < 4; nt++)
                #pragma unroll
                for (int e = 0; e < 4; e++) {
                    int half = e >> 1, p = e & 1;
                    int i = mt * 2 + half, k = nt * 2 + p;
                    int gi  = row0 + wr * 32 + mt * 16 + half * 8 + rbase;
                    int col = col0 + c * 64 + wc * 32 + nt * 8 + cpair + p;
                    float dist = sqi[i] + sqjt[k] - 2.f * acc[mt][nt][e];
                    dist = fmaxf(dist, 0.f);
                    float ev = exp2f(dist * NEGC);
                    bool self = (gi == col);
                    if (self) ev = 1.f;
                    float nv = (labi[i] == labjt[k] && !self) ? ev : 0.f;
                    rs_d[i] += ev;  rs_n[i] += nv;
                    cs_d[k] += ev;  cs_n[k] += nv;
                }

        if (!diag) {
            #pragma unroll
            for (int k = 0; k < 8; k++) {
                cs_d[k] += __shfl_xor_sync(0xFFFFFFFFu, cs_d[k], 4);
                cs_d[k] += __shfl_xor_sync(0xFFFFFFFFu, cs_d[k], 8);
                cs_d[k] += __shfl_xor_sync(0xFFFFFFFFu, cs_d[k], 16);
                cs_n[k] += __shfl_xor_sync(0xFFFFFFFFu, cs_n[k], 4);
                cs_n[k] += __shfl_xor_sync(0xFFFFFFFFu, cs_n[k], 8);
                cs_n[k] += __shfl_xor_sync(0xFFFFFFFFu, cs_n[k], 16);
            }
            __syncthreads();
            if (lane < 4) {
                #pragma unroll
                for (int k = 0; k < 8; k++) {
                    int cloc = wc * 32 + (k >> 1) * 8 + lane * 2 + (k & 1);
                    colD[wr * 64 + cloc] = cs_d[k];
                    colN[wr * 64 + cloc] = cs_n[k];
                }
            }
            __syncthreads();
            if (tid < 64) {
                float sd = 0.f, sn = 0.f;
                #pragma unroll
                for (int s = 0; s < 8; s++) { sd += colD[s * 64 + tid]; sn += colN[s * 64 + tid]; }
                g_pd[bi][col0 + c * 64 + tid] = sd;
                g_pn[bi][col0 + c * 64 + tid] = sn;
            }
        }
        __syncthreads();
    }

    #pragma unroll
    for (int i = 0; i < 4; i++) {
        rs_d[i] += __shfl_xor_sync(0xFFFFFFFFu, rs_d[i], 1);
        rs_d[i] += __shfl_xor_sync(0xFFFFFFFFu, rs_d[i], 2);
        rs_n[i] += __shfl_xor_sync(0xFFFFFFFFu, rs_n[i], 1);
        rs_n[i] += __shfl_xor_sync(0xFFFFFFFFu, rs_n[i], 2);
    }
    if ((lane & 3) == 0) {
        #pragma unroll
        for (int i = 0; i < 4; i++) {
            int rloc = wr * 32 + (i >> 1) * 16 + (i & 1) * 8 + rbase;
            rowD[wc * 256 + rloc] = rs_d[i];
            rowN[wc * 256 + rloc] = rs_n[i];
        }
    }
    __syncthreads();
    if (tid < 256) {
        g_pd[bj][row0 + tid] = rowD[tid] + rowD[256 + tid];
        g_pn[bj][row0 + tid] = rowN[tid] + rowN[256 + tid];
    }

    // ---------------- phase 2: last CTA reduces the loss ---------------------
    __threadfence();
    __syncthreads();
    int* flag = reinterpret_cast<int*>(smem + SM_MB + 24);
    if (tid == 0) {
        unsigned int old = atomicAdd(&g_cnt2, 1u);
        *flag = (old == (unsigned)(NTILES - 1)) ? 1 : 0;
    }
    __syncthreads();
    if (*flag) {
        __threadfence();   // acquire all CTAs' partial writes
        float s = 0.f;
        #pragma unroll
        for (int j = 0; j < 8; j++) {
            int i = tid + j * NT;
            float den = 0.f, num = 0.f;
            #pragma unroll
            for (int p = 0; p < NBLK; p++) { den += g_pd[p][i]; num += g_pn[p][i]; }
            s += logf(den) - logf(num);
        }
        float* sred = reinterpret_cast<float*>(smem);   // tiles dead now
        __syncthreads();
        sred[tid] = s;
        __syncthreads();
        for (int off = NT / 2; off > 0; off >>= 1) {
            if (tid < off) sred[tid] += sred[tid + off];
            __syncthreads();
        }
        if (tid == 0) {
            out[0] = sred[0] / (float)B;
            atomicExch(&g_sync1, 0u);   // self-reset for graph replays
            atomicExch(&g_cnt2, 0u);
        }
    }
}

// ---------------------------------------------------------------------------
extern "C" void kernel_launch(void* const* d_in, const int* in_sizes, int n_in,
                              void* d_out, int out_size) {
    const float* x = (const float*)d_in[0];
    const int*   y = (const int*)d_in[1];
    float* out = (float*)d_out;

    cudaFuncSetAttribute(snn_all, cudaFuncAttributeMaxDynamicSharedMemorySize, SMEM_SZ);
    snn_all<<<NTILES, NT, SMEM_SZ>>>(x, y, out);
}

// round 13
// speedup vs baseline: 1.1651x; 1.1651x over previous
#include <cuda_runtime.h>
#include <cuda_bf16.h>
#include <cstdint>

#define B 4096
#define D 128
#define TEMP 100.0f
#define NT 512
#define NBLK 16                        // 256-row blocks
#define NTILES (NBLK * (NBLK + 1) / 2) // 136
#define BS (B * 64)                    // elems per plane
#define PLANE (BS * 2)                 // bytes per plane

// smem map
#define SM_A     0                     // Ah0,Ah1 : 2 x 32768
#define SM_B     65536                 // 2 bufs x (Bh0,Bh1 : 2 x 8192)
#define SM_META  98304                 // sqr[256] sqc[256] labr[256] labc[256]
#define SM_RED   102400                // rowD[512] rowN[512]
#define SM_COLD  106496                // colD[4][8][64] = 8192 B
#define SM_COLN  114688                // colN[4][8][64] = 8192 B
#define SM_MB    122880                // mbA, mbB0, mbB1, mbE0, mbE1
#define SMEM_SZ  123008

__device__ __align__(1024) __nv_bfloat16 g_xs[2 * BS];
__device__ __align__(16) float g_sq[B];
__device__ int   g_lab[B];
__device__ float g_pd[NBLK][B];
__device__ float g_pn[NBLK][B];
__device__ float g_part[16];
__device__ unsigned int g_cnt;

__device__ __forceinline__ uint32_t smem_to_u32(const void* p) {
    uint32_t a;
    asm("{ .reg .u64 t; cvta.to.shared.u64 t, %1; cvt.u32.u64 %0, t; }"
        : "=r"(a) : "l"(p));
    return a;
}
__device__ __forceinline__ uint32_t swz(uint32_t x) { return x ^ ((x >> 3) & 0x70); }

#define MBAR_INIT(m, c) \
    asm volatile("mbarrier.init.shared.b64 [%0], %1;" \
                 :: "r"((uint32_t)(m)), "r"((uint32_t)(c)) : "memory")
#define MBAR_EXPECT(m, n) \
    asm volatile("mbarrier.arrive.expect_tx.shared.b64 _, [%0], %1;" \
                 :: "r"((uint32_t)(m)), "r"((uint32_t)(n)) : "memory")
#define MBAR_ARRIVE(m) \
    asm volatile("mbarrier.arrive.shared.b64 _, [%0];" \
                 :: "r"((uint32_t)(m)) : "memory")
#define MBAR_WAIT(m, par) do { \
    uint32_t _m = (uint32_t)(m); uint32_t _p = (uint32_t)(par); uint32_t _d; \
    asm volatile("{\n\t.reg .pred p;\n\t" \
        "mbarrier.try_wait.parity.acquire.cta.shared::cta.b64 p, [%1], %2;\n\t" \
        "selp.b32 %0, 1, 0, p;\n\t}" : "=r"(_d) : "r"(_m), "r"(_p) : "memory"); \
    if (!_d) { \
        asm volatile("{\n\t.reg .pred P1;\n\t" \
            "WL_%=:\n\t" \
            "mbarrier.try_wait.parity.acquire.cta.shared::cta.b64 P1, [%0], %1, 0x989680;\n\t" \
            "@P1 bra.uni WD_%=;\n\tbra.uni WL_%=;\n\tWD_%=:\n\t}" \
            :: "r"(_m), "r"(_p) : "memory"); \
    } } while (0)

__device__ __forceinline__ void bulk_cp(uint32_t dst, const void* src,
                                        uint32_t bytes, uint32_t mbar) {
    asm volatile(
        "cp.async.bulk.shared::cluster.global.mbarrier::complete_tx::bytes "
        "[%0], [%1], %2, [%3];"
        :: "r"(dst), "l"(src), "r"(bytes), "r"(mbar) : "memory");
}

#define LDSM_X4(r0, r1, r2, r3, addr) \
    asm volatile("ldmatrix.sync.aligned.m8n8.x4.shared.b16 {%0,%1,%2,%3}, [%4];" \
                 : "=r"(r0), "=r"(r1), "=r"(r2), "=r"(r3) : "r"(addr))
#define MMA16816(c, a, b0, b1) \
    asm volatile("mma.sync.aligned.m16n8k16.row.col.f32.bf16.bf16.f32 " \
                 "{%0,%1,%2,%3}, {%4,%5,%6,%7}, {%8,%9}, {%0,%1,%2,%3};" \
                 : "+f"((c)[0]), "+f"((c)[1]), "+f"((c)[2]), "+f"((c)[3]) \
                 : "r"((a)[0]), "r"((a)[1]), "r"((a)[2]), "r"((a)[3]), \
                   "r"(b0), "r"(b1))

// ---------------------------------------------------------------------------
// Prep (R11 verbatim): 4 rows per warp, norm + label + bf16 pre-swizzled split.
// ---------------------------------------------------------------------------
__global__ void snn_prep(const float* __restrict__ x, const int* __restrict__ y) {
    if (blockIdx.x == 0 && threadIdx.x == 0) g_cnt = 0;
    const int wrp = (blockIdx.x * blockDim.x + threadIdx.x) >> 5;
    const int lane = threadIdx.x & 31;
    const int gw0 = wrp * 4;

    float4 v[4];
    #pragma unroll
    for (int r = 0; r < 4; r++)
        v[r] = reinterpret_cast<const float4*>(x + (size_t)(gw0 + r) * D)[lane];

    const int k = lane * 4;
    const int hseg = k >> 6;
    char* base = reinterpret_cast<char*>(g_xs) + (size_t)hseg * PLANE;

    #pragma unroll
    for (int r = 0; r < 4; r++) {
        float s = v[r].x * v[r].x + v[r].y * v[r].y
                + v[r].z * v[r].z + v[r].w * v[r].w;
        #pragma unroll
        for (int o = 16; o; o >>= 1) s += __shfl_xor_sync(0xFFFFFFFFu, s, o);
        __nv_bfloat16 h[4];
        h[0] = __float2bfloat16(v[r].x);  h[1] = __float2bfloat16(v[r].y);
        h[2] = __float2bfloat16(v[r].z);  h[3] = __float2bfloat16(v[r].w);
        uint32_t sby = swz((uint32_t)(gw0 + r) * 128 + (k & 63) * 2);
        *reinterpret_cast<uint2*>(base + sby) = *reinterpret_cast<uint2*>(h);
        if (lane == 0) { g_sq[gw0 + r] = s; g_lab[gw0 + r] = y[gw0 + r]; }
    }
}

// One K=128 MMA pass over a 32x32 warp tile. (R7 verbatim)
__device__ __forceinline__ void mma_pass(float acc[2][4][4],
                                         uint32_t abase, uint32_t bbase,
                                         uint32_t bstride,
                                         uint32_t pa, uint32_t pb) {
    #pragma unroll
    for (int ks = 0; ks < 8; ks++) {
        const uint32_t koff = (ks & 3) * 32;
        const uint32_t ka = abase + (ks >> 2) * 32768;
        const uint32_t kb = bbase + (ks >> 2) * bstride;
        uint32_t a0[4], a1[4], b0[4], b1[4];
        LDSM_X4(a0[0], a0[1], a0[2], a0[3], ka + swz(pa + koff));
        LDSM_X4(a1[0], a1[1], a1[2], a1[3], ka + swz(pa + 2048 + koff));
        LDSM_X4(b0[0], b0[1], b0[2], b0[3], kb + swz(pb + koff));
        LDSM_X4(b1[0], b1[1], b1[2], b1[3], kb + swz(pb + 2048 + koff));
        MMA16816(acc[0][0], a0, b0[0], b0[1]);
        MMA16816(acc[0][1], a0, b0[2], b0[3]);
        MMA16816(acc[0][2], a0, b1[0], b1[1]);
        MMA16816(acc[0][3], a0, b1[2], b1[3]);
        MMA16816(acc[1][0], a1, b0[0], b0[1]);
        MMA16816(acc[1][1], a1, b0[2], b0[3]);
        MMA16816(acc[1][2], a1, b1[0], b1[1]);
        MMA16816(acc[1][3], a1, b1[2], b1[3]);
    }
}

// ---------------------------------------------------------------------------
// Main: R7 tiling, but NO intra-loop __syncthreads. B-buffer reuse guarded by
// empty-mbarriers (16 warp arrivals); col sums go to per-chunk smem buffers
// and are reduced once after the loop. Warps free-run across chunks.
// ---------------------------------------------------------------------------
__global__ void __launch_bounds__(NT, 1)
snn_main() {
    extern __shared__ char smem[];
    uint32_t sb = smem_to_u32(smem);
    const int tid = threadIdx.x;
    const int lane = tid & 31;
    const int w = tid >> 5, wr = w >> 1, wc = w & 1;
    const int grp = lane >> 3, l7 = lane & 7;
    const float NEGC = -1.4426950408889634f / TEMP;

    int t = blockIdx.x, bi = 0;
    while (t >= NBLK - bi) { t -= NBLK - bi; bi++; }
    const int bj = bi + t;
    const bool diag = (bi == bj);
    const int row0 = bi * 256, col0 = bj * 256;

    const uint32_t mbA  = sb + SM_MB;
    const uint32_t mbB0 = sb + SM_MB + 8;
    const uint32_t mbB1 = sb + SM_MB + 16;
    const uint32_t mbE0 = sb + SM_MB + 24;
    const uint32_t mbE1 = sb + SM_MB + 32;

    if (tid == 0) {
        MBAR_INIT(mbA, 1); MBAR_INIT(mbB0, 1); MBAR_INIT(mbB1, 1);
        MBAR_INIT(mbE0, 16); MBAR_INIT(mbE1, 16);
    }
    __syncthreads();

    const char* gx = reinterpret_cast<const char*>(g_xs);
    if (tid == 0) {
        MBAR_EXPECT(mbA, 65536);
        #pragma unroll
        for (int s = 0; s < 2; s++)
            bulk_cp(sb + SM_A + s * 32768,
                    gx + (size_t)s * PLANE + (size_t)row0 * 128, 32768, mbA);
        if (!diag) {
            MBAR_EXPECT(mbB0, 16384);
            #pragma unroll
            for (int s = 0; s < 2; s++)
                bulk_cp(sb + SM_B + s * 8192,
                        gx + (size_t)s * PLANE + (size_t)col0 * 128, 8192, mbB0);
        }
    }

    float* sqr  = reinterpret_cast<float*>(smem + SM_META);
    float* sqc  = sqr + 256;
    int*   labr = reinterpret_cast<int*>(sqc + 256);
    int*   labc = labr + 256;
    {
        int i = tid;
        if (i < 256) { sqr[i] = g_sq[row0 + i];  labr[i] = g_lab[row0 + i]; }
        else         { sqc[i - 256] = g_sq[col0 + i - 256];
                       labc[i - 256] = g_lab[col0 + i - 256]; }
    }
    __syncthreads();

    const uint32_t pa = (uint32_t)((wr * 32 + (grp & 1) * 8 + l7) * 128 + (grp >> 1) * 16);
    const uint32_t pb = (uint32_t)((wc * 32 + (grp >> 1) * 8 + l7) * 128 + (grp & 1) * 16);
    const int rbase = lane >> 2, cpair = (lane & 3) * 2;

    float sqi[4]; int labi[4];
    #pragma unroll
    for (int i = 0; i < 4; i++) {
        int rloc = wr * 32 + (i >> 1) * 16 + (i & 1) * 8 + rbase;
        sqi[i] = sqr[rloc];  labi[i] = labr[rloc];
    }
    float rs_d[4] = {0.f, 0.f, 0.f, 0.f}, rs_n[4] = {0.f, 0.f, 0.f, 0.f};

    float* rowD = reinterpret_cast<float*>(smem + SM_RED);
    float* rowN = rowD + 512;
    float* colD = reinterpret_cast<float*>(smem + SM_COLD);  // [4][8][64]
    float* colN = reinterpret_cast<float*>(smem + SM_COLN);

    MBAR_WAIT(mbA, 0);

    for (int c = 0; c < 4; c++) {
        if (!diag) {
            if (tid == 0 && c < 3) {
                // chunk c+1 into buf (c+1)&1; for c>=1 that buf was used by
                // chunk c-1 -> wait its 16 LDSM-done arrivals (first phase).
                uint32_t mb = (c & 1) ? mbB0 : mbB1;
                if (c >= 1) MBAR_WAIT((c & 1) ? mbE0 : mbE1, 0);
                MBAR_EXPECT(mb, 16384);
                #pragma unroll
                for (int s = 0; s < 2; s++)
                    bulk_cp(sb + SM_B + (uint32_t)(((c + 1) & 1) * 16384 + s * 8192),
                            gx + (size_t)s * PLANE
                               + (size_t)(col0 + (c + 1) * 64) * 128, 8192, mb);
            }
            MBAR_WAIT((c & 1) ? mbB1 : mbB0, (c >> 1) & 1);
        }

        float acc[2][4][4];
        #pragma unroll
        for (int mt = 0; mt < 2; mt++)
            #pragma unroll
            for (int nt = 0; nt < 4; nt++)
                #pragma unroll
                for (int e = 0; e < 4; e++) acc[mt][nt][e] = 0.f;

        uint32_t bH, bstr;
        if (diag) { bH = sb + SM_A + c * 8192;  bstr = 32768; }
        else      { bH = sb + SM_B + (uint32_t)((c & 1) * 16384);  bstr = 8192; }
        mma_pass(acc, sb + SM_A, bH, bstr, pa, pb);

        // this warp is done reading buf (c&1): signal empty
        if (!diag && lane == 0) MBAR_ARRIVE((c & 1) ? mbE1 : mbE0);

        // ---- epilogue for this 256x64 chunk ----
        float sqjt[8]; int labjt[8];
        #pragma unroll
        for (int k = 0; k < 8; k++) {
            int cloc = c * 64 + wc * 32 + (k >> 1) * 8 + cpair + (k & 1);
            sqjt[k] = diag ? sqr[cloc] : sqc[cloc];
            labjt[k] = diag ? labr[cloc] : labc[cloc];
        }
        float cs_d[8] = {0,0,0,0,0,0,0,0}, cs_n[8] = {0,0,0,0,0,0,0,0};

        #pragma unroll
        for (int mt = 0; mt < 2; mt++)
            #pragma unroll
            for (int nt = 0; nt < 4; nt++)
                #pragma unroll
                for (int e = 0; e < 4; e++) {
                    int half = e >> 1, p = e & 1;
                    int i = mt * 2 + half, k = nt * 2 + p;
                    int gi  = row0 + wr * 32 + mt * 16 + half * 8 + rbase;
                    int col = col0 + c * 64 + wc * 32 + nt * 8 + cpair + p;
                    float dist = sqi[i] + sqjt[k] - 2.f * acc[mt][nt][e];
                    dist = fmaxf(dist, 0.f);
                    float ev = exp2f(dist * NEGC);
                    bool self = (gi == col);
                    if (self) ev = 1.f;
                    float nv = (labi[i] == labjt[k] && !self) ? ev : 0.f;
                    rs_d[i] += ev;  rs_n[i] += nv;
                    cs_d[k] += ev;  cs_n[k] += nv;
                }

        if (!diag) {
            #pragma unroll
            for (int k = 0; k < 8; k++) {
                cs_d[k] += __shfl_xor_sync(0xFFFFFFFFu, cs_d[k], 4);
                cs_d[k] += __shfl_xor_sync(0xFFFFFFFFu, cs_d[k], 8);
                cs_d[k] += __shfl_xor_sync(0xFFFFFFFFu, cs_d[k], 16);
                cs_n[k] += __shfl_xor_sync(0xFFFFFFFFu, cs_n[k], 4);
                cs_n[k] += __shfl_xor_sync(0xFFFFFFFFu, cs_n[k], 8);
                cs_n[k] += __shfl_xor_sync(0xFFFFFFFFu, cs_n[k], 16);
            }
            if (lane < 4) {
                // per-chunk private buffer: no barrier needed
                #pragma unroll
                for (int k = 0; k < 8; k++) {
                    int cloc = wc * 32 + (k >> 1) * 8 + lane * 2 + (k & 1);
                    colD[c * 512 + wr * 64 + cloc] = cs_d[k];
                    colN[c * 512 + wr * 64 + cloc] = cs_n[k];
                }
            }
        }
    }

    // ---- row-sum cross-warp reduce ----
    #pragma unroll
    for (int i = 0; i < 4; i++) {
        rs_d[i] += __shfl_xor_sync(0xFFFFFFFFu, rs_d[i], 1);
        rs_d[i] += __shfl_xor_sync(0xFFFFFFFFu, rs_d[i], 2);
        rs_n[i] += __shfl_xor_sync(0xFFFFFFFFu, rs_n[i], 1);
        rs_n[i] += __shfl_xor_sync(0xFFFFFFFFu, rs_n[i], 2);
    }
    if ((lane & 3) == 0) {
        #pragma unroll
        for (int i = 0; i < 4; i++) {
            int rloc = wr * 32 + (i >> 1) * 16 + (i & 1) * 8 + rbase;
            rowD[wc * 256 + rloc] = rs_d[i];
            rowN[wc * 256 + rloc] = rs_n[i];
        }
    }
    __syncthreads();    // single barrier: all rowD/colD writes complete

    if (tid < 256) {
        g_pd[bj][row0 + tid] = rowD[tid] + rowD[256 + tid];
        g_pn[bj][row0 + tid] = rowN[tid] + rowN[256 + tid];
        if (!diag) {
            int c = tid >> 6, col = tid & 63;
            float sd = 0.f, sn = 0.f;
            #pragma unroll
            for (int s = 0; s < 8; s++) {
                sd += colD[c * 512 + s * 64 + col];
                sn += colN[c * 512 + s * 64 + col];
            }
            g_pd[bi][col0 + c * 64 + col] = sd;
            g_pn[bi][col0 + c * 64 + col] = sn;
        }
    }
}

// ---------------------------------------------------------------------------
// Finalize (R11 verbatim): counter-gated single kernel.
// ---------------------------------------------------------------------------
__global__ void snn_fin(float* __restrict__ out) {
    __shared__ float sred[256];
    int i = blockIdx.x * 256 + threadIdx.x;
    float den = 0.f, num = 0.f;
    #pragma unroll
    for (int p = 0; p < NBLK; p++) { den += g_pd[p][i]; num += g_pn[p][i]; }
    float s = logf(den) - logf(num);
    sred[threadIdx.x] = s;
    __syncthreads();
    for (int off = 128; off > 0; off >>= 1) {
        if (threadIdx.x < off) sred[threadIdx.x] += sred[threadIdx.x + off];
        __syncthreads();
    }
    if (threadIdx.x == 0) {
        g_part[blockIdx.x] = sred[0];
        __threadfence();
        unsigned int old = atomicAdd(&g_cnt, 1u);
        if (old == 15u) {
            float tot = 0.f;
            #pragma unroll
            for (int b = 0; b < 16; b++) tot += g_part[b];
            out[0] = tot / (float)B;
        }
    }
}

// ---------------------------------------------------------------------------
extern "C" void kernel_launch(void* const* d_in, const int* in_sizes, int n_in,
                              void* d_out, int out_size) {
    const float* x = (const float*)d_in[0];
    const int*   y = (const int*)d_in[1];
    float* out = (float*)d_out;

    cudaFuncSetAttribute(snn_main, cudaFuncAttributeMaxDynamicSharedMemorySize, SMEM_SZ);

    snn_prep<<<B / 32, 256>>>(x, y);
    snn_main<<<NTILES, NT, SMEM_SZ>>>();
    snn_fin<<<16, 256>>>(out);
}

// round 14
// speedup vs baseline: 1.1764x; 1.0097x over previous
#include <cuda_runtime.h>
#include <cuda_bf16.h>
#include <cstdint>

#define B 4096
#define D 128
#define TEMP 100.0f
#define NT 512
#define NBLK 16                        // 256-row blocks
#define NTILES (NBLK * (NBLK + 1) / 2) // 136
#define BS (B * 64)                    // elems per plane
#define PLANE (BS * 2)                 // bytes per plane

// smem map
#define SM_A     0                     // Ah0,Ah1 : 2 x 32768
#define SM_B     65536                 // 2 bufs x (Bh0,Bh1 : 2 x 8192)
#define SM_META  98304                 // sqr[256] sqc[256] labr[256] labc[256]
#define SM_RED   102400                // rowD[512] rowN[512]
#define SM_COLD  106496                // colD[4][8][64] = 8192 B
#define SM_COLN  114688                // colN[4][8][64] = 8192 B
#define SM_MB    122880                // mbA, mbB0, mbB1, mbE0, mbE1
#define SMEM_SZ  123008

__device__ __align__(1024) __nv_bfloat16 g_xs[2 * BS];
__device__ __align__(16) float g_sq[B];
__device__ int   g_lab[B];
__device__ float g_pd[NBLK][B];
__device__ float g_pn[NBLK][B];
__device__ float g_part[16];
__device__ unsigned int g_cnt;

__device__ __forceinline__ uint32_t smem_to_u32(const void* p) {
    uint32_t a;
    asm("{ .reg .u64 t; cvta.to.shared.u64 t, %1; cvt.u32.u64 %0, t; }"
        : "=r"(a) : "l"(p));
    return a;
}
__device__ __forceinline__ uint32_t swz(uint32_t x) { return x ^ ((x >> 3) & 0x70); }

// PDL primitives (sm_90 baseline PTX)
__device__ __forceinline__ void pdl_wait() {
    asm volatile("griddepcontrol.wait;" ::: "memory");
}
__device__ __forceinline__ void pdl_trigger() {
    asm volatile("griddepcontrol.launch_dependents;" ::: "memory");
}

#define MBAR_INIT(m, c) \
    asm volatile("mbarrier.init.shared.b64 [%0], %1;" \
                 :: "r"((uint32_t)(m)), "r"((uint32_t)(c)) : "memory")
#define MBAR_EXPECT(m, n) \
    asm volatile("mbarrier.arrive.expect_tx.shared.b64 _, [%0], %1;" \
                 :: "r"((uint32_t)(m)), "r"((uint32_t)(n)) : "memory")
#define MBAR_ARRIVE(m) \
    asm volatile("mbarrier.arrive.shared.b64 _, [%0];" \
                 :: "r"((uint32_t)(m)) : "memory")
#define MBAR_WAIT(m, par) do { \
    uint32_t _m = (uint32_t)(m); uint32_t _p = (uint32_t)(par); uint32_t _d; \
    asm volatile("{\n\t.reg .pred p;\n\t" \
        "mbarrier.try_wait.parity.acquire.cta.shared::cta.b64 p, [%1], %2;\n\t" \
        "selp.b32 %0, 1, 0, p;\n\t}" : "=r"(_d) : "r"(_m), "r"(_p) : "memory"); \
    if (!_d) { \
        asm volatile("{\n\t.reg .pred P1;\n\t" \
            "WL_%=:\n\t" \
            "mbarrier.try_wait.parity.acquire.cta.shared::cta.b64 P1, [%0], %1, 0x989680;\n\t" \
            "@P1 bra.uni WD_%=;\n\tbra.uni WL_%=;\n\tWD_%=:\n\t}" \
            :: "r"(_m), "r"(_p) : "memory"); \
    } } while (0)

__device__ __forceinline__ void bulk_cp(uint32_t dst, const void* src,
                                        uint32_t bytes, uint32_t mbar) {
    asm volatile(
        "cp.async.bulk.shared::cluster.global.mbarrier::complete_tx::bytes "
        "[%0], [%1], %2, [%3];"
        :: "r"(dst), "l"(src), "r"(bytes), "r"(mbar) : "memory");
}

#define LDSM_X4(r0, r1, r2, r3, addr) \
    asm volatile("ldmatrix.sync.aligned.m8n8.x4.shared.b16 {%0,%1,%2,%3}, [%4];" \
                 : "=r"(r0), "=r"(r1), "=r"(r2), "=r"(r3) : "r"(addr))
#define MMA16816(c, a, b0, b1) \
    asm volatile("mma.sync.aligned.m16n8k16.row.col.f32.bf16.bf16.f32 " \
                 "{%0,%1,%2,%3}, {%4,%5,%6,%7}, {%8,%9}, {%0,%1,%2,%3};" \
                 : "+f"((c)[0]), "+f"((c)[1]), "+f"((c)[2]), "+f"((c)[3]) \
                 : "r"((a)[0]), "r"((a)[1]), "r"((a)[2]), "r"((a)[3]), \
                   "r"(b0), "r"(b1))

// ---------------------------------------------------------------------------
// Prep: 4 rows per warp, norm + label + bf16 pre-swizzled split.
// Triggers dependent launch as soon as each CTA's stores are issued.
// ---------------------------------------------------------------------------
__global__ void snn_prep(const float* __restrict__ x, const int* __restrict__ y) {
    if (blockIdx.x == 0 && threadIdx.x == 0) g_cnt = 0;
    const int wrp = (blockIdx.x * blockDim.x + threadIdx.x) >> 5;
    const int lane = threadIdx.x & 31;
    const int gw0 = wrp * 4;

    float4 v[4];
    #pragma unroll
    for (int r = 0; r < 4; r++)
        v[r] = reinterpret_cast<const float4*>(x + (size_t)(gw0 + r) * D)[lane];

    const int k = lane * 4;
    const int hseg = k >> 6;
    char* base = reinterpret_cast<char*>(g_xs) + (size_t)hseg * PLANE;

    #pragma unroll
    for (int r = 0; r < 4; r++) {
        float s = v[r].x * v[r].x + v[r].y * v[r].y
                + v[r].z * v[r].z + v[r].w * v[r].w;
        #pragma unroll
        for (int o = 16; o; o >>= 1) s += __shfl_xor_sync(0xFFFFFFFFu, s, o);
        __nv_bfloat16 h[4];
        h[0] = __float2bfloat16(v[r].x);  h[1] = __float2bfloat16(v[r].y);
        h[2] = __float2bfloat16(v[r].z);  h[3] = __float2bfloat16(v[r].w);
        uint32_t sby = swz((uint32_t)(gw0 + r) * 128 + (k & 63) * 2);
        *reinterpret_cast<uint2*>(base + sby) = *reinterpret_cast<uint2*>(h);
        if (lane == 0) { g_sq[gw0 + r] = s; g_lab[gw0 + r] = y[gw0 + r]; }
    }
    pdl_trigger();
}

// One K=128 MMA pass over a 32x32 warp tile. (R7 verbatim)
__device__ __forceinline__ void mma_pass(float acc[2][4][4],
                                         uint32_t abase, uint32_t bbase,
                                         uint32_t bstride,
                                         uint32_t pa, uint32_t pb) {
    #pragma unroll
    for (int ks = 0; ks < 8; ks++) {
        const uint32_t koff = (ks & 3) * 32;
        const uint32_t ka = abase + (ks >> 2) * 32768;
        const uint32_t kb = bbase + (ks >> 2) * bstride;
        uint32_t a0[4], a1[4], b0[4], b1[4];
        LDSM_X4(a0[0], a0[1], a0[2], a0[3], ka + swz(pa + koff));
        LDSM_X4(a1[0], a1[1], a1[2], a1[3], ka + swz(pa + 2048 + koff));
        LDSM_X4(b0[0], b0[1], b0[2], b0[3], kb + swz(pb + koff));
        LDSM_X4(b1[0], b1[1], b1[2], b1[3], kb + swz(pb + 2048 + koff));
        MMA16816(acc[0][0], a0, b0[0], b0[1]);
        MMA16816(acc[0][1], a0, b0[2], b0[3]);
        MMA16816(acc[0][2], a0, b1[0], b1[1]);
        MMA16816(acc[0][3], a0, b1[2], b1[3]);
        MMA16816(acc[1][0], a1, b0[0], b0[1]);
        MMA16816(acc[1][1], a1, b0[2], b0[3]);
        MMA16816(acc[1][2], a1, b1[0], b1[1]);
        MMA16816(acc[1][3], a1, b1[2], b1[3]);
    }
}

// ---------------------------------------------------------------------------
// Main (R13 body + PDL): ramp overlaps prep; gridDepSync before first read.
// ---------------------------------------------------------------------------
__global__ void __launch_bounds__(NT, 1)
snn_main() {
    extern __shared__ char smem[];
    uint32_t sb = smem_to_u32(smem);
    const int tid = threadIdx.x;
    const int lane = tid & 31;
    const int w = tid >> 5, wr = w >> 1, wc = w & 1;
    const int grp = lane >> 3, l7 = lane & 7;
    const float NEGC = -1.4426950408889634f / TEMP;

    int t = blockIdx.x, bi = 0;
    while (t >= NBLK - bi) { t -= NBLK - bi; bi++; }
    const int bj = bi + t;
    const bool diag = (bi == bj);
    const int row0 = bi * 256, col0 = bj * 256;

    const uint32_t mbA  = sb + SM_MB;
    const uint32_t mbB0 = sb + SM_MB + 8;
    const uint32_t mbB1 = sb + SM_MB + 16;
    const uint32_t mbE0 = sb + SM_MB + 24;
    const uint32_t mbE1 = sb + SM_MB + 32;

    if (tid == 0) {
        MBAR_INIT(mbA, 1); MBAR_INIT(mbB0, 1); MBAR_INIT(mbB1, 1);
        MBAR_INIT(mbE0, 16); MBAR_INIT(mbE1, 16);
    }
    __syncthreads();

    pdl_wait();   // prep's g_xs / g_sq / g_lab writes visible from here on

    const char* gx = reinterpret_cast<const char*>(g_xs);
    if (tid == 0) {
        MBAR_EXPECT(mbA, 65536);
        #pragma unroll
        for (int s = 0; s < 2; s++)
            bulk_cp(sb + SM_A + s * 32768,
                    gx + (size_t)s * PLANE + (size_t)row0 * 128, 32768, mbA);
        if (!diag) {
            MBAR_EXPECT(mbB0, 16384);
            #pragma unroll
            for (int s = 0; s < 2; s++)
                bulk_cp(sb + SM_B + s * 8192,
                        gx + (size_t)s * PLANE + (size_t)col0 * 128, 8192, mbB0);
        }
    }

    float* sqr  = reinterpret_cast<float*>(smem + SM_META);
    float* sqc  = sqr + 256;
    int*   labr = reinterpret_cast<int*>(sqc + 256);
    int*   labc = labr + 256;
    {
        int i = tid;
        if (i < 256) { sqr[i] = g_sq[row0 + i];  labr[i] = g_lab[row0 + i]; }
        else         { sqc[i - 256] = g_sq[col0 + i - 256];
                       labc[i - 256] = g_lab[col0 + i - 256]; }
    }
    __syncthreads();

    const uint32_t pa = (uint32_t)((wr * 32 + (grp & 1) * 8 + l7) * 128 + (grp >> 1) * 16);
    const uint32_t pb = (uint32_t)((wc * 32 + (grp >> 1) * 8 + l7) * 128 + (grp & 1) * 16);
    const int rbase = lane >> 2, cpair = (lane & 3) * 2;

    float sqi[4]; int labi[4];
    #pragma unroll
    for (int i = 0; i < 4; i++) {
        int rloc = wr * 32 + (i >> 1) * 16 + (i & 1) * 8 + rbase;
        sqi[i] = sqr[rloc];  labi[i] = labr[rloc];
    }
    float rs_d[4] = {0.f, 0.f, 0.f, 0.f}, rs_n[4] = {0.f, 0.f, 0.f, 0.f};

    float* rowD = reinterpret_cast<float*>(smem + SM_RED);
    float* rowN = rowD + 512;
    float* colD = reinterpret_cast<float*>(smem + SM_COLD);  // [4][8][64]
    float* colN = reinterpret_cast<float*>(smem + SM_COLN);

    MBAR_WAIT(mbA, 0);

    for (int c = 0; c < 4; c++) {
        if (!diag) {
            if (tid == 0 && c < 3) {
                uint32_t mb = (c & 1) ? mbB0 : mbB1;
                if (c >= 1) MBAR_WAIT((c & 1) ? mbE0 : mbE1, 0);
                MBAR_EXPECT(mb, 16384);
                #pragma unroll
                for (int s = 0; s < 2; s++)
                    bulk_cp(sb + SM_B + (uint32_t)(((c + 1) & 1) * 16384 + s * 8192),
                            gx + (size_t)s * PLANE
                               + (size_t)(col0 + (c + 1) * 64) * 128, 8192, mb);
            }
            MBAR_WAIT((c & 1) ? mbB1 : mbB0, (c >> 1) & 1);
        }

        float acc[2][4][4];
        #pragma unroll
        for (int mt = 0; mt < 2; mt++)
            #pragma unroll
            for (int nt = 0; nt < 4; nt++)
                #pragma unroll
                for (int e = 0; e < 4; e++) acc[mt][nt][e] = 0.f;

        uint32_t bH, bstr;
        if (diag) { bH = sb + SM_A + c * 8192;  bstr = 32768; }
        else      { bH = sb + SM_B + (uint32_t)((c & 1) * 16384);  bstr = 8192; }
        mma_pass(acc, sb + SM_A, bH, bstr, pa, pb);

        if (!diag && lane == 0) MBAR_ARRIVE((c & 1) ? mbE1 : mbE0);

        float sqjt[8]; int labjt[8];
        #pragma unroll
        for (int k = 0; k < 8; k++) {
            int cloc = c * 64 + wc * 32 + (k >> 1) * 8 + cpair + (k & 1);
            sqjt[k] = diag ? sqr[cloc] : sqc[cloc];
            labjt[k] = diag ? labr[cloc] : labc[cloc];
        }
        float cs_d[8] = {0,0,0,0,0,0,0,0}, cs_n[8] = {0,0,0,0,0,0,0,0};

        #pragma unroll
        for (int mt = 0; mt < 2; mt++)
            #pragma unroll
            for (int nt = 0; nt < 4; nt++)
                #pragma unroll
                for (int e = 0; e < 4; e++) {
                    int half = e >> 1, p = e & 1;
                    int i = mt * 2 + half, k = nt * 2 + p;
                    int gi  = row0 + wr * 32 + mt * 16 + half * 8 + rbase;
                    int col = col0 + c * 64 + wc * 32 + nt * 8 + cpair + p;
                    float dist = sqi[i] + sqjt[k] - 2.f * acc[mt][nt][e];
                    dist = fmaxf(dist, 0.f);
                    float ev = exp2f(dist * NEGC);
                    bool self = (gi == col);
                    if (self) ev = 1.f;
                    float nv = (labi[i] == labjt[k] && !self) ? ev : 0.f;
                    rs_d[i] += ev;  rs_n[i] += nv;
                    cs_d[k] += ev;  cs_n[k] += nv;
                }

        if (!diag) {
            #pragma unroll
            for (int k = 0; k < 8; k++) {
                cs_d[k] += __shfl_xor_sync(0xFFFFFFFFu, cs_d[k], 4);
                cs_d[k] += __shfl_xor_sync(0xFFFFFFFFu, cs_d[k], 8);
                cs_d[k] += __shfl_xor_sync(0xFFFFFFFFu, cs_d[k], 16);
                cs_n[k] += __shfl_xor_sync(0xFFFFFFFFu, cs_n[k], 4);
                cs_n[k] += __shfl_xor_sync(0xFFFFFFFFu, cs_n[k], 8);
                cs_n[k] += __shfl_xor_sync(0xFFFFFFFFu, cs_n[k], 16);
            }
            if (lane < 4) {
                #pragma unroll
                for (int k = 0; k < 8; k++) {
                    int cloc = wc * 32 + (k >> 1) * 8 + lane * 2 + (k & 1);
                    colD[c * 512 + wr * 64 + cloc] = cs_d[k];
                    colN[c * 512 + wr * 64 + cloc] = cs_n[k];
                }
            }
        }
    }

    #pragma unroll
    for (int i = 0; i < 4; i++) {
        rs_d[i] += __shfl_xor_sync(0xFFFFFFFFu, rs_d[i], 1);
        rs_d[i] += __shfl_xor_sync(0xFFFFFFFFu, rs_d[i], 2);
        rs_n[i] += __shfl_xor_sync(0xFFFFFFFFu, rs_n[i], 1);
        rs_n[i] += __shfl_xor_sync(0xFFFFFFFFu, rs_n[i], 2);
    }
    if ((lane & 3) == 0) {
        #pragma unroll
        for (int i = 0; i < 4; i++) {
            int rloc = wr * 32 + (i >> 1) * 16 + (i & 1) * 8 + rbase;
            rowD[wc * 256 + rloc] = rs_d[i];
            rowN[wc * 256 + rloc] = rs_n[i];
        }
    }
    __syncthreads();

    if (tid < 256) {
        g_pd[bj][row0 + tid] = rowD[tid] + rowD[256 + tid];
        g_pn[bj][row0 + tid] = rowN[tid] + rowN[256 + tid];
        if (!diag) {
            int c = tid >> 6, col = tid & 63;
            float sd = 0.f, sn = 0.f;
            #pragma unroll
            for (int s = 0; s < 8; s++) {
                sd += colD[c * 512 + s * 64 + col];
                sn += colN[c * 512 + s * 64 + col];
            }
            g_pd[bi][col0 + c * 64 + col] = sd;
            g_pn[bi][col0 + c * 64 + col] = sn;
        }
    }
    pdl_trigger();
}

// ---------------------------------------------------------------------------
// Finalize: counter-gated single kernel, PDL-overlapped ramp.
// ---------------------------------------------------------------------------
__global__ void snn_fin(float* __restrict__ out) {
    __shared__ float sred[256];
    pdl_wait();   // main's g_pd / g_pn visible from here on
    int i = blockIdx.x * 256 + threadIdx.x;
    float den = 0.f, num = 0.f;
    #pragma unroll
    for (int p = 0; p < NBLK; p++) { den += g_pd[p][i]; num += g_pn[p][i]; }
    float s = logf(den) - logf(num);
    sred[threadIdx.x] = s;
    __syncthreads();
    for (int off = 128; off > 0; off >>= 1) {
        if (threadIdx.x < off) sred[threadIdx.x] += sred[threadIdx.x + off];
        __syncthreads();
    }
    if (threadIdx.x == 0) {
        g_part[blockIdx.x] = sred[0];
        __threadfence();
        unsigned int old = atomicAdd(&g_cnt, 1u);
        if (old == 15u) {
            float tot = 0.f;
            #pragma unroll
            for (int b = 0; b < 16; b++) tot += g_part[b];
            out[0] = tot / (float)B;
        }
    }
}

// ---------------------------------------------------------------------------
extern "C" void kernel_launch(void* const* d_in, const int* in_sizes, int n_in,
                              void* d_out, int out_size) {
    const float* x = (const float*)d_in[0];
    const int*   y = (const int*)d_in[1];
    float* out = (float*)d_out;

    cudaFuncSetAttribute(snn_main, cudaFuncAttributeMaxDynamicSharedMemorySize, SMEM_SZ);

    snn_prep<<<B / 32, 256>>>(x, y);

    cudaLaunchAttribute attr[1];
    attr[0].id = cudaLaunchAttributeProgrammaticStreamSerialization;
    attr[0].val.programmaticStreamSerializationAllowed = 1;

    {
        cudaLaunchConfig_t cfg = {};
        cfg.gridDim = dim3(NTILES, 1, 1);
        cfg.blockDim = dim3(NT, 1, 1);
        cfg.dynamicSmemBytes = SMEM_SZ;
        cfg.attrs = attr;
        cfg.numAttrs = 1;
        cudaLaunchKernelEx(&cfg, snn_main);
    }
    {
        cudaLaunchConfig_t cfg = {};
        cfg.gridDim = dim3(16, 1, 1);
        cfg.blockDim = dim3(256, 1, 1);
        cfg.dynamicSmemBytes = 0;
        cfg.attrs = attr;
        cfg.numAttrs = 1;
        cudaLaunchKernelEx(&cfg, snn_fin, out);
    }
}

// round 15
// speedup vs baseline: 1.2567x; 1.0682x over previous
#include <cuda_runtime.h>
#include <cuda_bf16.h>
#include <cstdint>

#define B 4096
#define D 128
#define TEMP 100.0f
#define NT 512
#define NBLK 16                        // 256-row blocks
#define NTILES (NBLK * (NBLK + 1) / 2) // 136
#define BS (B * 64)                    // elems per plane
#define PLANE (BS * 2)                 // bytes per plane

// smem map
#define SM_A     0                     // Ah0,Ah1 : 2 x 32768
#define SM_B     65536                 // 2 bufs x (Bh0,Bh1 : 2 x 8192)
#define SM_META  98304                 // sqr[256] sqc[256] labr[256] labc[256]
#define SM_RED   102400                // rowD[512] rowN[512]
#define SM_COLD  106496                // colD[4][8][64] = 8192 B
#define SM_COLN  114688                // colN[4][8][64] = 8192 B
#define SM_MB    122880                // mbA, mbB0, mbB1, mbE0, mbE1
#define SMEM_SZ  123008

__device__ __align__(1024) __nv_bfloat16 g_xs[2 * BS];
__device__ __align__(16) float g_sq[B];
__device__ int   g_lab[B];
__device__ float g_pd[NBLK][B];
__device__ float g_pn[NBLK][B];
__device__ float g_part[16];
__device__ unsigned int g_cnt;

__device__ __forceinline__ uint32_t smem_to_u32(const void* p) {
    uint32_t a;
    asm("{ .reg .u64 t; cvta.to.shared.u64 t, %1; cvt.u32.u64 %0, t; }"
        : "=r"(a) : "l"(p));
    return a;
}
__device__ __forceinline__ uint32_t swz(uint32_t x) { return x ^ ((x >> 3) & 0x70); }

// bare MUFU.EX2 (no libdevice wrapper)
__device__ __forceinline__ float ex2_fast(float x) {
    float r;
    asm("ex2.approx.ftz.f32 %0, %1;" : "=f"(r) : "f"(x));
    return r;
}

__device__ __forceinline__ void pdl_wait() {
    asm volatile("griddepcontrol.wait;" ::: "memory");
}
__device__ __forceinline__ void pdl_trigger() {
    asm volatile("griddepcontrol.launch_dependents;" ::: "memory");
}

#define MBAR_INIT(m, c) \
    asm volatile("mbarrier.init.shared.b64 [%0], %1;" \
                 :: "r"((uint32_t)(m)), "r"((uint32_t)(c)) : "memory")
#define MBAR_EXPECT(m, n) \
    asm volatile("mbarrier.arrive.expect_tx.shared.b64 _, [%0], %1;" \
                 :: "r"((uint32_t)(m)), "r"((uint32_t)(n)) : "memory")
#define MBAR_ARRIVE(m) \
    asm volatile("mbarrier.arrive.shared.b64 _, [%0];" \
                 :: "r"((uint32_t)(m)) : "memory")
#define MBAR_WAIT(m, par) do { \
    uint32_t _m = (uint32_t)(m); uint32_t _p = (uint32_t)(par); uint32_t _d; \
    asm volatile("{\n\t.reg .pred p;\n\t" \
        "mbarrier.try_wait.parity.acquire.cta.shared::cta.b64 p, [%1], %2;\n\t" \
        "selp.b32 %0, 1, 0, p;\n\t}" : "=r"(_d) : "r"(_m), "r"(_p) : "memory"); \
    if (!_d) { \
        asm volatile("{\n\t.reg .pred P1;\n\t" \
            "WL_%=:\n\t" \
            "mbarrier.try_wait.parity.acquire.cta.shared::cta.b64 P1, [%0], %1, 0x989680;\n\t" \
            "@P1 bra.uni WD_%=;\n\tbra.uni WL_%=;\n\tWD_%=:\n\t}" \
            :: "r"(_m), "r"(_p) : "memory"); \
    } } while (0)

__device__ __forceinline__ void bulk_cp(uint32_t dst, const void* src,
                                        uint32_t bytes, uint32_t mbar) {
    asm volatile(
        "cp.async.bulk.shared::cluster.global.mbarrier::complete_tx::bytes "
        "[%0], [%1], %2, [%3];"
        :: "r"(dst), "l"(src), "r"(bytes), "r"(mbar) : "memory");
}

#define LDSM_X4(r0, r1, r2, r3, addr) \
    asm volatile("ldmatrix.sync.aligned.m8n8.x4.shared.b16 {%0,%1,%2,%3}, [%4];" \
                 : "=r"(r0), "=r"(r1), "=r"(r2), "=r"(r3) : "r"(addr))
#define MMA16816(c, a, b0, b1) \
    asm volatile("mma.sync.aligned.m16n8k16.row.col.f32.bf16.bf16.f32 " \
                 "{%0,%1,%2,%3}, {%4,%5,%6,%7}, {%8,%9}, {%0,%1,%2,%3};" \
                 : "+f"((c)[0]), "+f"((c)[1]), "+f"((c)[2]), "+f"((c)[3]) \
                 : "r"((a)[0]), "r"((a)[1]), "r"((a)[2]), "r"((a)[3]), \
                   "r"(b0), "r"(b1))

// ---------------------------------------------------------------------------
// Prep: 4 rows per warp, norm + label + bf16 pre-swizzled split.
// ---------------------------------------------------------------------------
__global__ void snn_prep(const float* __restrict__ x, const int* __restrict__ y) {
    if (blockIdx.x == 0 && threadIdx.x == 0) g_cnt = 0;
    const int wrp = (blockIdx.x * blockDim.x + threadIdx.x) >> 5;
    const int lane = threadIdx.x & 31;
    const int gw0 = wrp * 4;

    float4 v[4];
    #pragma unroll
    for (int r = 0; r < 4; r++)
        v[r] = reinterpret_cast<const float4*>(x + (size_t)(gw0 + r) * D)[lane];

    const int k = lane * 4;
    const int hseg = k >> 6;
    char* base = reinterpret_cast<char*>(g_xs) + (size_t)hseg * PLANE;

    #pragma unroll
    for (int r = 0; r < 4; r++) {
        float s = v[r].x * v[r].x + v[r].y * v[r].y
                + v[r].z * v[r].z + v[r].w * v[r].w;
        #pragma unroll
        for (int o = 16; o; o >>= 1) s += __shfl_xor_sync(0xFFFFFFFFu, s, o);
        __nv_bfloat16 h[4];
        h[0] = __float2bfloat16(v[r].x);  h[1] = __float2bfloat16(v[r].y);
        h[2] = __float2bfloat16(v[r].z);  h[3] = __float2bfloat16(v[r].w);
        uint32_t sby = swz((uint32_t)(gw0 + r) * 128 + (k & 63) * 2);
        *reinterpret_cast<uint2*>(base + sby) = *reinterpret_cast<uint2*>(h);
        if (lane == 0) { g_sq[gw0 + r] = s; g_lab[gw0 + r] = y[gw0 + r]; }
    }
    pdl_trigger();
}

// One K=128 MMA pass over a 32x32 warp tile. (R7 verbatim)
__device__ __forceinline__ void mma_pass(float acc[2][4][4],
                                         uint32_t abase, uint32_t bbase,
                                         uint32_t bstride,
                                         uint32_t pa, uint32_t pb) {
    #pragma unroll
    for (int ks = 0; ks < 8; ks++) {
        const uint32_t koff = (ks & 3) * 32;
        const uint32_t ka = abase + (ks >> 2) * 32768;
        const uint32_t kb = bbase + (ks >> 2) * bstride;
        uint32_t a0[4], a1[4], b0[4], b1[4];
        LDSM_X4(a0[0], a0[1], a0[2], a0[3], ka + swz(pa + koff));
        LDSM_X4(a1[0], a1[1], a1[2], a1[3], ka + swz(pa + 2048 + koff));
        LDSM_X4(b0[0], b0[1], b0[2], b0[3], kb + swz(pb + koff));
        LDSM_X4(b1[0], b1[1], b1[2], b1[3], kb + swz(pb + 2048 + koff));
        MMA16816(acc[0][0], a0, b0[0], b0[1]);
        MMA16816(acc[0][1], a0, b0[2], b0[3]);
        MMA16816(acc[0][2], a0, b1[0], b1[1]);
        MMA16816(acc[0][3], a0, b1[2], b1[3]);
        MMA16816(acc[1][0], a1, b0[0], b0[1]);
        MMA16816(acc[1][1], a1, b0[2], b0[3]);
        MMA16816(acc[1][2], a1, b1[0], b1[1]);
        MMA16816(acc[1][3], a1, b1[2], b1[3]);
    }
}

// ---------------------------------------------------------------------------
// Main: R13/R14 body; epilogue uses bare EX2 + precomputed match masks.
// ---------------------------------------------------------------------------
__global__ void __launch_bounds__(NT, 1)
snn_main() {
    extern __shared__ char smem[];
    uint32_t sb = smem_to_u32(smem);
    const int tid = threadIdx.x;
    const int lane = tid & 31;
    const int w = tid >> 5, wr = w >> 1, wc = w & 1;
    const int grp = lane >> 3, l7 = lane & 7;
    const float NEGC = -1.4426950408889634f / TEMP;

    int t = blockIdx.x, bi = 0;
    while (t >= NBLK - bi) { t -= NBLK - bi; bi++; }
    const int bj = bi + t;
    const bool diag = (bi == bj);
    const int row0 = bi * 256, col0 = bj * 256;

    const uint32_t mbA  = sb + SM_MB;
    const uint32_t mbB0 = sb + SM_MB + 8;
    const uint32_t mbB1 = sb + SM_MB + 16;
    const uint32_t mbE0 = sb + SM_MB + 24;
    const uint32_t mbE1 = sb + SM_MB + 32;

    if (tid == 0) {
        MBAR_INIT(mbA, 1); MBAR_INIT(mbB0, 1); MBAR_INIT(mbB1, 1);
        MBAR_INIT(mbE0, 16); MBAR_INIT(mbE1, 16);
    }
    __syncthreads();

    pdl_wait();

    const char* gx = reinterpret_cast<const char*>(g_xs);
    if (tid == 0) {
        MBAR_EXPECT(mbA, 65536);
        #pragma unroll
        for (int s = 0; s < 2; s++)
            bulk_cp(sb + SM_A + s * 32768,
                    gx + (size_t)s * PLANE + (size_t)row0 * 128, 32768, mbA);
        if (!diag) {
            MBAR_EXPECT(mbB0, 16384);
            #pragma unroll
            for (int s = 0; s < 2; s++)
                bulk_cp(sb + SM_B + s * 8192,
                        gx + (size_t)s * PLANE + (size_t)col0 * 128, 8192, mbB0);
        }
    }

    float* sqr  = reinterpret_cast<float*>(smem + SM_META);
    float* sqc  = sqr + 256;
    int*   labr = reinterpret_cast<int*>(sqc + 256);
    int*   labc = labr + 256;
    {
        int i = tid;
        if (i < 256) { sqr[i] = g_sq[row0 + i];  labr[i] = g_lab[row0 + i]; }
        else         { sqc[i - 256] = g_sq[col0 + i - 256];
                       labc[i - 256] = g_lab[col0 + i - 256]; }
    }
    __syncthreads();

    const uint32_t pa = (uint32_t)((wr * 32 + (grp & 1) * 8 + l7) * 128 + (grp >> 1) * 16);
    const uint32_t pb = (uint32_t)((wc * 32 + (grp >> 1) * 8 + l7) * 128 + (grp & 1) * 16);
    const int rbase = lane >> 2, cpair = (lane & 3) * 2;

    float sqi[4]; int labi[4]; int gi_[4];
    #pragma unroll
    for (int i = 0; i < 4; i++) {
        int rloc = wr * 32 + (i >> 1) * 16 + (i & 1) * 8 + rbase;
        sqi[i] = sqr[rloc];  labi[i] = labr[rloc];
        gi_[i] = row0 + rloc;
    }
    float rs_d[4] = {0.f, 0.f, 0.f, 0.f}, rs_n[4] = {0.f, 0.f, 0.f, 0.f};

    float* rowD = reinterpret_cast<float*>(smem + SM_RED);
    float* rowN = rowD + 512;
    float* colD = reinterpret_cast<float*>(smem + SM_COLD);
    float* colN = reinterpret_cast<float*>(smem + SM_COLN);

    MBAR_WAIT(mbA, 0);

    for (int c = 0; c < 4; c++) {
        if (!diag) {
            if (tid == 0 && c < 3) {
                uint32_t mb = (c & 1) ? mbB0 : mbB1;
                if (c >= 1) MBAR_WAIT((c & 1) ? mbE0 : mbE1, 0);
                MBAR_EXPECT(mb, 16384);
                #pragma unroll
                for (int s = 0; s < 2; s++)
                    bulk_cp(sb + SM_B + (uint32_t)(((c + 1) & 1) * 16384 + s * 8192),
                            gx + (size_t)s * PLANE
                               + (size_t)(col0 + (c + 1) * 64) * 128, 8192, mb);
            }
            MBAR_WAIT((c & 1) ? mbB1 : mbB0, (c >> 1) & 1);
        }

        float acc[2][4][4];
        #pragma unroll
        for (int mt = 0; mt < 2; mt++)
            #pragma unroll
            for (int nt = 0; nt < 4; nt++)
                #pragma unroll
                for (int e = 0; e < 4; e++) acc[mt][nt][e] = 0.f;

        uint32_t bH, bstr;
        if (diag) { bH = sb + SM_A + c * 8192;  bstr = 32768; }
        else      { bH = sb + SM_B + (uint32_t)((c & 1) * 16384);  bstr = 8192; }
        mma_pass(acc, sb + SM_A, bH, bstr, pa, pb);

        if (!diag && lane == 0) MBAR_ARRIVE((c & 1) ? mbE1 : mbE0);

        // ---- epilogue: precompute per-(i,k) masks, then tight FMA/EX2 loop --
        float sqjt[8];
        int   colg[8];
        #pragma unroll
        for (int k = 0; k < 8; k++) {
            int cloc = c * 64 + wc * 32 + (k >> 1) * 8 + cpair + (k & 1);
            sqjt[k] = diag ? sqr[cloc] : sqc[cloc];
            colg[k] = col0 + cloc;
        }
        // same/self masks (computed once per chunk: 32 compares, not 128)
        float same[4][8];
        #pragma unroll
        for (int i = 0; i < 4; i++) {
            #pragma unroll
            for (int k = 0; k < 8; k++) {
                int lj = diag ? labr[colg[k] - col0] : labc[colg[k] - col0];
                bool self = diag && (gi_[i] == colg[k]);
                same[i][k] = (labi[i] == lj && !self) ? 1.f : 0.f;
            }
        }

        float cs_d[8] = {0,0,0,0,0,0,0,0}, cs_n[8] = {0,0,0,0,0,0,0,0};

        #pragma unroll
        for (int mt = 0; mt < 2; mt++)
            #pragma unroll
            for (int nt = 0; nt < 4; nt++)
                #pragma unroll
                for (int e = 0; e < 4; e++) {
                    int half = e >> 1, p = e & 1;
                    int i = mt * 2 + half, k = nt * 2 + p;
                    float dist = sqi[i] + sqjt[k] - 2.f * acc[mt][nt][e];
                    dist = fmaxf(dist, 0.f);
                    float ev = ex2_fast(dist * NEGC);
                    if (diag && gi_[i] == colg[k]) ev = 1.f;
                    float nv = ev * same[i][k];
                    rs_d[i] += ev;  rs_n[i] += nv;
                    cs_d[k] += ev;  cs_n[k] += nv;
                }

        if (!diag) {
            #pragma unroll
            for (int k = 0; k < 8; k++) {
                cs_d[k] += __shfl_xor_sync(0xFFFFFFFFu, cs_d[k], 4);
                cs_d[k] += __shfl_xor_sync(0xFFFFFFFFu, cs_d[k], 8);
                cs_d[k] += __shfl_xor_sync(0xFFFFFFFFu, cs_d[k], 16);
                cs_n[k] += __shfl_xor_sync(0xFFFFFFFFu, cs_n[k], 4);
                cs_n[k] += __shfl_xor_sync(0xFFFFFFFFu, cs_n[k], 8);
                cs_n[k] += __shfl_xor_sync(0xFFFFFFFFu, cs_n[k], 16);
            }
            if (lane < 4) {
                #pragma unroll
                for (int k = 0; k < 8; k++) {
                    int cloc = wc * 32 + (k >> 1) * 8 + lane * 2 + (k & 1);
                    colD[c * 512 + wr * 64 + cloc] = cs_d[k];
                    colN[c * 512 + wr * 64 + cloc] = cs_n[k];
                }
            }
        }
    }

    #pragma unroll
    for (int i = 0; i < 4; i++) {
        rs_d[i] += __shfl_xor_sync(0xFFFFFFFFu, rs_d[i], 1);
        rs_d[i] += __shfl_xor_sync(0xFFFFFFFFu, rs_d[i], 2);
        rs_n[i] += __shfl_xor_sync(0xFFFFFFFFu, rs_n[i], 1);
        rs_n[i] += __shfl_xor_sync(0xFFFFFFFFu, rs_n[i], 2);
    }
    if ((lane & 3) == 0) {
        #pragma unroll
        for (int i = 0; i < 4; i++) {
            int rloc = wr * 32 + (i >> 1) * 16 + (i & 1) * 8 + rbase;
            rowD[wc * 256 + rloc] = rs_d[i];
            rowN[wc * 256 + rloc] = rs_n[i];
        }
    }
    __syncthreads();

    if (tid < 256) {
        g_pd[bj][row0 + tid] = rowD[tid] + rowD[256 + tid];
        g_pn[bj][row0 + tid] = rowN[tid] + rowN[256 + tid];
        if (!diag) {
            int c = tid >> 6, col = tid & 63;
            float sd = 0.f, sn = 0.f;
            #pragma unroll
            for (int s = 0; s < 8; s++) {
                sd += colD[c * 512 + s * 64 + col];
                sn += colN[c * 512 + s * 64 + col];
            }
            g_pd[bi][col0 + c * 64 + col] = sd;
            g_pn[bi][col0 + c * 64 + col] = sn;
        }
    }
    pdl_trigger();
}

// ---------------------------------------------------------------------------
// Finalize: counter-gated single kernel, PDL-overlapped ramp.
// ---------------------------------------------------------------------------
__global__ void snn_fin(float* __restrict__ out) {
    __shared__ float sred[256];
    pdl_wait();
    int i = blockIdx.x * 256 + threadIdx.x;
    float den = 0.f, num = 0.f;
    #pragma unroll
    for (int p = 0; p < NBLK; p++) { den += g_pd[p][i]; num += g_pn[p][i]; }
    float s = logf(den) - logf(num);
    sred[threadIdx.x] = s;
    __syncthreads();
    for (int off = 128; off > 0; off >>= 1) {
        if (threadIdx.x < off) sred[threadIdx.x] += sred[threadIdx.x + off];
        __syncthreads();
    }
    if (threadIdx.x == 0) {
        g_part[blockIdx.x] = sred[0];
        __threadfence();
        unsigned int old = atomicAdd(&g_cnt, 1u);
        if (old == 15u) {
            float tot = 0.f;
            #pragma unroll
            for (int b = 0; b < 16; b++) tot += g_part[b];
            out[0] = tot / (float)B;
        }
    }
}

// ---------------------------------------------------------------------------
extern "C" void kernel_launch(void* const* d_in, const int* in_sizes, int n_in,
                              void* d_out, int out_size) {
    const float* x = (const float*)d_in[0];
    const int*   y = (const int*)d_in[1];
    float* out = (float*)d_out;

    cudaFuncSetAttribute(snn_main, cudaFuncAttributeMaxDynamicSharedMemorySize, SMEM_SZ);

    snn_prep<<<B / 32, 256>>>(x, y);

    cudaLaunchAttribute attr[1];
    attr[0].id = cudaLaunchAttributeProgrammaticStreamSerialization;
    attr[0].val.programmaticStreamSerializationAllowed = 1;

    {
        cudaLaunchConfig_t cfg = {};
        cfg.gridDim = dim3(NTILES, 1, 1);
        cfg.blockDim = dim3(NT, 1, 1);
        cfg.dynamicSmemBytes = SMEM_SZ;
        cfg.attrs = attr;
        cfg.numAttrs = 1;
        cudaLaunchKernelEx(&cfg, snn_main);
    }
    {
        cudaLaunchConfig_t cfg = {};
        cfg.gridDim = dim3(16, 1, 1);
        cfg.blockDim = dim3(256, 1, 1);
        cfg.dynamicSmemBytes = 0;
        cfg.attrs = attr;
        cfg.numAttrs = 1;
        cudaLaunchKernelEx(&cfg, snn_fin, out);
    }
}

// round 16
// speedup vs baseline: 1.4307x; 1.1385x over previous
#include <cuda_runtime.h>
#include <cuda_bf16.h>
#include <cstdint>

#define B 4096
#define D 128
#define TEMP 100.0f
#define NT 512
#define NBLK 16                        // 256-row blocks
#define NTILES (NBLK * (NBLK + 1) / 2) // 136
#define BS (B * 64)                    // elems per plane
#define PLANE (BS * 2)                 // bytes per plane

// smem map
#define SM_A     0                     // Ah0,Ah1 : 2 x 32768
#define SM_B     65536                 // 2 bufs x (Bh0,Bh1 : 2 x 8192)
#define SM_META  98304                 // sqr[256] sqc[256] labr[256] labc[256]
#define SM_RED   102400                // rowD[512] rowN[512]
#define SM_COLD  106496                // colD[4][8][64] = 8192 B
#define SM_COLN  114688                // colN[4][8][64] = 8192 B
#define SM_MB    122880                // mbA, mbB0, mbB1, mbE0, mbE1
#define SMEM_SZ  123008

__device__ __align__(1024) __nv_bfloat16 g_xs[2 * BS];
__device__ __align__(16) float g_sq[B];
__device__ int   g_lab[B];
__device__ float g_pd[NBLK][B];
__device__ float g_pn[NBLK][B];
__device__ float g_part[16];
__device__ unsigned int g_cnt;

typedef unsigned long long u64;

__device__ __forceinline__ uint32_t smem_to_u32(const void* p) {
    uint32_t a;
    asm("{ .reg .u64 t; cvta.to.shared.u64 t, %1; cvt.u32.u64 %0, t; }"
        : "=r"(a) : "l"(p));
    return a;
}
__device__ __forceinline__ uint32_t swz(uint32_t x) { return x ^ ((x >> 3) & 0x70); }

__device__ __forceinline__ float ex2_fast(float x) {
    float r;
    asm("ex2.approx.ftz.f32 %0, %1;" : "=f"(r) : "f"(x));
    return r;
}

// packed f32x2 (Blackwell)
#define PACKF2(out, lo, hi) \
    asm("mov.b64 %0, {%1, %2};" : "=l"(out) : "f"(lo), "f"(hi))
#define UNPACKF2(lo, hi, in) \
    asm("mov.b64 {%0, %1}, %2;" : "=f"(lo), "=f"(hi) : "l"(in))
#define ADDF2(out, a, b) \
    asm("add.rn.f32x2 %0, %1, %2;" : "=l"(out) : "l"(a), "l"(b))
#define FMAF2(out, a, b, c) \
    asm("fma.rn.f32x2 %0, %1, %2, %3;" : "=l"(out) : "l"(a), "l"(b), "l"(c))

__device__ __forceinline__ void pdl_wait() {
    asm volatile("griddepcontrol.wait;" ::: "memory");
}
__device__ __forceinline__ void pdl_trigger() {
    asm volatile("griddepcontrol.launch_dependents;" ::: "memory");
}

#define MBAR_INIT(m, c) \
    asm volatile("mbarrier.init.shared.b64 [%0], %1;" \
                 :: "r"((uint32_t)(m)), "r"((uint32_t)(c)) : "memory")
#define MBAR_EXPECT(m, n) \
    asm volatile("mbarrier.arrive.expect_tx.shared.b64 _, [%0], %1;" \
                 :: "r"((uint32_t)(m)), "r"((uint32_t)(n)) : "memory")
#define MBAR_ARRIVE(m) \
    asm volatile("mbarrier.arrive.shared.b64 _, [%0];" \
                 :: "r"((uint32_t)(m)) : "memory")
#define MBAR_WAIT(m, par) do { \
    uint32_t _m = (uint32_t)(m); uint32_t _p = (uint32_t)(par); uint32_t _d; \
    asm volatile("{\n\t.reg .pred p;\n\t" \
        "mbarrier.try_wait.parity.acquire.cta.shared::cta.b64 p, [%1], %2;\n\t" \
        "selp.b32 %0, 1, 0, p;\n\t}" : "=r"(_d) : "r"(_m), "r"(_p) : "memory"); \
    if (!_d) { \
        asm volatile("{\n\t.reg .pred P1;\n\t" \
            "WL_%=:\n\t" \
            "mbarrier.try_wait.parity.acquire.cta.shared::cta.b64 P1, [%0], %1, 0x989680;\n\t" \
            "@P1 bra.uni WD_%=;\n\tbra.uni WL_%=;\n\tWD_%=:\n\t}" \
            :: "r"(_m), "r"(_p) : "memory"); \
    } } while (0)

__device__ __forceinline__ void bulk_cp(uint32_t dst, const void* src,
                                        uint32_t bytes, uint32_t mbar) {
    asm volatile(
        "cp.async.bulk.shared::cluster.global.mbarrier::complete_tx::bytes "
        "[%0], [%1], %2, [%3];"
        :: "r"(dst), "l"(src), "r"(bytes), "r"(mbar) : "memory");
}

#define LDSM_X4(r0, r1, r2, r3, addr) \
    asm volatile("ldmatrix.sync.aligned.m8n8.x4.shared.b16 {%0,%1,%2,%3}, [%4];" \
                 : "=r"(r0), "=r"(r1), "=r"(r2), "=r"(r3) : "r"(addr))
#define MMA16816(c, a, b0, b1) \
    asm volatile("mma.sync.aligned.m16n8k16.row.col.f32.bf16.bf16.f32 " \
                 "{%0,%1,%2,%3}, {%4,%5,%6,%7}, {%8,%9}, {%0,%1,%2,%3};" \
                 : "+f"((c)[0]), "+f"((c)[1]), "+f"((c)[2]), "+f"((c)[3]) \
                 : "r"((a)[0]), "r"((a)[1]), "r"((a)[2]), "r"((a)[3]), \
                   "r"(b0), "r"(b1))

// ---------------------------------------------------------------------------
// Prep: 4 rows per warp, norm + label + bf16 pre-swizzled split.
// ---------------------------------------------------------------------------
__global__ void snn_prep(const float* __restrict__ x, const int* __restrict__ y) {
    if (blockIdx.x == 0 && threadIdx.x == 0) g_cnt = 0;
    const int wrp = (blockIdx.x * blockDim.x + threadIdx.x) >> 5;
    const int lane = threadIdx.x & 31;
    const int gw0 = wrp * 4;

    float4 v[4];
    #pragma unroll
    for (int r = 0; r < 4; r++)
        v[r] = reinterpret_cast<const float4*>(x + (size_t)(gw0 + r) * D)[lane];

    const int k = lane * 4;
    const int hseg = k >> 6;
    char* base = reinterpret_cast<char*>(g_xs) + (size_t)hseg * PLANE;

    #pragma unroll
    for (int r = 0; r < 4; r++) {
        float s = v[r].x * v[r].x + v[r].y * v[r].y
                + v[r].z * v[r].z + v[r].w * v[r].w;
        #pragma unroll
        for (int o = 16; o; o >>= 1) s += __shfl_xor_sync(0xFFFFFFFFu, s, o);
        __nv_bfloat16 h[4];
        h[0] = __float2bfloat16(v[r].x);  h[1] = __float2bfloat16(v[r].y);
        h[2] = __float2bfloat16(v[r].z);  h[3] = __float2bfloat16(v[r].w);
        uint32_t sby = swz((uint32_t)(gw0 + r) * 128 + (k & 63) * 2);
        *reinterpret_cast<uint2*>(base + sby) = *reinterpret_cast<uint2*>(h);
        if (lane == 0) { g_sq[gw0 + r] = s; g_lab[gw0 + r] = y[gw0 + r]; }
    }
    pdl_trigger();
}

// One K=128 MMA pass over a 32x32 warp tile. (R7 verbatim)
__device__ __forceinline__ void mma_pass(float acc[2][4][4],
                                         uint32_t abase, uint32_t bbase,
                                         uint32_t bstride,
                                         uint32_t pa, uint32_t pb) {
    #pragma unroll
    for (int ks = 0; ks < 8; ks++) {
        const uint32_t koff = (ks & 3) * 32;
        const uint32_t ka = abase + (ks >> 2) * 32768;
        const uint32_t kb = bbase + (ks >> 2) * bstride;
        uint32_t a0[4], a1[4], b0[4], b1[4];
        LDSM_X4(a0[0], a0[1], a0[2], a0[3], ka + swz(pa + koff));
        LDSM_X4(a1[0], a1[1], a1[2], a1[3], ka + swz(pa + 2048 + koff));
        LDSM_X4(b0[0], b0[1], b0[2], b0[3], kb + swz(pb + koff));
        LDSM_X4(b1[0], b1[1], b1[2], b1[3], kb + swz(pb + 2048 + koff));
        MMA16816(acc[0][0], a0, b0[0], b0[1]);
        MMA16816(acc[0][1], a0, b0[2], b0[3]);
        MMA16816(acc[0][2], a0, b1[0], b1[1]);
        MMA16816(acc[0][3], a0, b1[2], b1[3]);
        MMA16816(acc[1][0], a1, b0[0], b0[1]);
        MMA16816(acc[1][1], a1, b0[2], b0[3]);
        MMA16816(acc[1][2], a1, b1[0], b1[1]);
        MMA16816(acc[1][3], a1, b1[2], b1[3]);
    }
}

// ---------------------------------------------------------------------------
// Main: R15 structure; epilogue in packed f32x2 (FFMA2 path).
// ---------------------------------------------------------------------------
__global__ void __launch_bounds__(NT, 1)
snn_main() {
    extern __shared__ char smem[];
    uint32_t sb = smem_to_u32(smem);
    const int tid = threadIdx.x;
    const int lane = tid & 31;
    const int w = tid >> 5, wr = w >> 1, wc = w & 1;
    const int grp = lane >> 3, l7 = lane & 7;
    const float NEGC = -1.4426950408889634f / TEMP;   // -log2e/T
    const float C2s  = 2.0f * 1.4426950408889634f / TEMP;

    int t = blockIdx.x, bi = 0;
    while (t >= NBLK - bi) { t -= NBLK - bi; bi++; }
    const int bj = bi + t;
    const bool diag = (bi == bj);
    const int row0 = bi * 256, col0 = bj * 256;

    const uint32_t mbA  = sb + SM_MB;
    const uint32_t mbB0 = sb + SM_MB + 8;
    const uint32_t mbB1 = sb + SM_MB + 16;
    const uint32_t mbE0 = sb + SM_MB + 24;
    const uint32_t mbE1 = sb + SM_MB + 32;

    if (tid == 0) {
        MBAR_INIT(mbA, 1); MBAR_INIT(mbB0, 1); MBAR_INIT(mbB1, 1);
        MBAR_INIT(mbE0, 16); MBAR_INIT(mbE1, 16);
    }
    __syncthreads();

    pdl_wait();

    const char* gx = reinterpret_cast<const char*>(g_xs);
    if (tid == 0) {
        MBAR_EXPECT(mbA, 65536);
        #pragma unroll
        for (int s = 0; s < 2; s++)
            bulk_cp(sb + SM_A + s * 32768,
                    gx + (size_t)s * PLANE + (size_t)row0 * 128, 32768, mbA);
        if (!diag) {
            MBAR_EXPECT(mbB0, 16384);
            #pragma unroll
            for (int s = 0; s < 2; s++)
                bulk_cp(sb + SM_B + s * 8192,
                        gx + (size_t)s * PLANE + (size_t)col0 * 128, 8192, mbB0);
        }
    }

    float* sqr  = reinterpret_cast<float*>(smem + SM_META);
    float* sqc  = sqr + 256;
    int*   labr = reinterpret_cast<int*>(sqc + 256);
    int*   labc = labr + 256;
    {
        int i = tid;
        if (i < 256) { sqr[i] = g_sq[row0 + i];  labr[i] = g_lab[row0 + i]; }
        else         { sqc[i - 256] = g_sq[col0 + i - 256];
                       labc[i - 256] = g_lab[col0 + i - 256]; }
    }
    __syncthreads();

    const uint32_t pa = (uint32_t)((wr * 32 + (grp & 1) * 8 + l7) * 128 + (grp >> 1) * 16);
    const uint32_t pb = (uint32_t)((wc * 32 + (grp >> 1) * 8 + l7) * 128 + (grp & 1) * 16);
    const int rbase = lane >> 2, cpair = (lane & 3) * 2;

    float sqi[4]; int labi[4]; int gi_[4];
    #pragma unroll
    for (int i = 0; i < 4; i++) {
        int rloc = wr * 32 + (i >> 1) * 16 + (i & 1) * 8 + rbase;
        sqi[i] = sqr[rloc];  labi[i] = labr[rloc];
        gi_[i] = row0 + rloc;
    }
    // ci2[i] = pack(sqi*NEGC, sqi*NEGC); C22 = pack(C2s, C2s)
    u64 ci2[4], C22;
    PACKF2(C22, C2s, C2s);
    #pragma unroll
    for (int i = 0; i < 4; i++) {
        float c = sqi[i] * NEGC;
        PACKF2(ci2[i], c, c);
    }
    u64 rsd2[4], rsn2[4];
    #pragma unroll
    for (int i = 0; i < 4; i++) { rsd2[i] = 0ull; rsn2[i] = 0ull; }

    float* rowD = reinterpret_cast<float*>(smem + SM_RED);
    float* rowN = rowD + 512;
    float* colD = reinterpret_cast<float*>(smem + SM_COLD);
    float* colN = reinterpret_cast<float*>(smem + SM_COLN);

    MBAR_WAIT(mbA, 0);

    for (int c = 0; c < 4; c++) {
        if (!diag) {
            if (tid == 0 && c < 3) {
                uint32_t mb = (c & 1) ? mbB0 : mbB1;
                if (c >= 1) MBAR_WAIT((c & 1) ? mbE0 : mbE1, 0);
                MBAR_EXPECT(mb, 16384);
                #pragma unroll
                for (int s = 0; s < 2; s++)
                    bulk_cp(sb + SM_B + (uint32_t)(((c + 1) & 1) * 16384 + s * 8192),
                            gx + (size_t)s * PLANE
                               + (size_t)(col0 + (c + 1) * 64) * 128, 8192, mb);
            }
            MBAR_WAIT((c & 1) ? mbB1 : mbB0, (c >> 1) & 1);
        }

        float acc[2][4][4];
        #pragma unroll
        for (int mt = 0; mt < 2; mt++)
            #pragma unroll
            for (int nt = 0; nt < 4; nt++)
                #pragma unroll
                for (int e = 0; e < 4; e++) acc[mt][nt][e] = 0.f;

        uint32_t bH, bstr;
        if (diag) { bH = sb + SM_A + c * 8192;  bstr = 32768; }
        else      { bH = sb + SM_B + (uint32_t)((c & 1) * 16384);  bstr = 8192; }
        mma_pass(acc, sb + SM_A, bH, bstr, pa, pb);

        if (!diag && lane == 0) MBAR_ARRIVE((c & 1) ? mbE1 : mbE0);

        // ---- packed-f32x2 epilogue for this 256x64 chunk ----
        int labjt[8];
        u64 cj2[4];
        #pragma unroll
        for (int nt = 0; nt < 4; nt++) {
            int cl0 = c * 64 + wc * 32 + nt * 8 + cpair;
            float j0 = (diag ? sqr[cl0]     : sqc[cl0])     * NEGC;
            float j1 = (diag ? sqr[cl0 + 1] : sqc[cl0 + 1]) * NEGC;
            PACKF2(cj2[nt], j0, j1);
            labjt[2 * nt]     = diag ? labr[cl0]     : labc[cl0];
            labjt[2 * nt + 1] = diag ? labr[cl0 + 1] : labc[cl0 + 1];
        }

        u64 csd2[4], csn2[4];
        #pragma unroll
        for (int nt = 0; nt < 4; nt++) { csd2[nt] = 0ull; csn2[nt] = 0ull; }

        #pragma unroll
        for (int mt = 0; mt < 2; mt++)
            #pragma unroll
            for (int half = 0; half < 2; half++) {
                const int i = mt * 2 + half;
                #pragma unroll
                for (int nt = 0; nt < 4; nt++) {
                    u64 acc2, base2, arg2;
                    PACKF2(acc2, acc[mt][nt][half * 2], acc[mt][nt][half * 2 + 1]);
                    ADDF2(base2, ci2[i], cj2[nt]);
                    FMAF2(arg2, acc2, C22, base2);
                    float a0, a1;
                    UNPACKF2(a0, a1, arg2);
                    float e0 = ex2_fast(a0), e1 = ex2_fast(a1);
                    u64 ev2;
                    PACKF2(ev2, e0, e1);
                    // match mask (1.0/0.0), self zeroed on diag tiles
                    float m0 = (labi[i] == labjt[2 * nt])     ? 1.f : 0.f;
                    float m1 = (labi[i] == labjt[2 * nt + 1]) ? 1.f : 0.f;
                    if (diag) {
                        int cg = col0 + c * 64 + wc * 32 + nt * 8 + cpair;
                        if (gi_[i] == cg)     m0 = 0.f;
                        if (gi_[i] == cg + 1) m1 = 0.f;
                    }
                    u64 msk2;
                    PACKF2(msk2, m0, m1);
                    ADDF2(rsd2[i], rsd2[i], ev2);
                    FMAF2(rsn2[i], ev2, msk2, rsn2[i]);
                    ADDF2(csd2[nt], csd2[nt], ev2);
                    FMAF2(csn2[nt], ev2, msk2, csn2[nt]);
                }
            }

        if (!diag) {
            float cs_d[8], cs_n[8];
            #pragma unroll
            for (int nt = 0; nt < 4; nt++) {
                UNPACKF2(cs_d[2 * nt], cs_d[2 * nt + 1], csd2[nt]);
                UNPACKF2(cs_n[2 * nt], cs_n[2 * nt + 1], csn2[nt]);
            }
            #pragma unroll
            for (int k = 0; k < 8; k++) {
                cs_d[k] += __shfl_xor_sync(0xFFFFFFFFu, cs_d[k], 4);
                cs_d[k] += __shfl_xor_sync(0xFFFFFFFFu, cs_d[k], 8);
                cs_d[k] += __shfl_xor_sync(0xFFFFFFFFu, cs_d[k], 16);
                cs_n[k] += __shfl_xor_sync(0xFFFFFFFFu, cs_n[k], 4);
                cs_n[k] += __shfl_xor_sync(0xFFFFFFFFu, cs_n[k], 8);
                cs_n[k] += __shfl_xor_sync(0xFFFFFFFFu, cs_n[k], 16);
            }
            if (lane < 4) {
                #pragma unroll
                for (int k = 0; k < 8; k++) {
                    int cloc = wc * 32 + (k >> 1) * 8 + lane * 2 + (k & 1);
                    colD[c * 512 + wr * 64 + cloc] = cs_d[k];
                    colN[c * 512 + wr * 64 + cloc] = cs_n[k];
                }
            }
        }
    }

    // ---- merge packed row sums, cross-warp reduce ----
    float rs_d[4], rs_n[4];
    #pragma unroll
    for (int i = 0; i < 4; i++) {
        float lo, hi;
        UNPACKF2(lo, hi, rsd2[i]);  rs_d[i] = lo + hi;
        UNPACKF2(lo, hi, rsn2[i]);  rs_n[i] = lo + hi;
    }
    #pragma unroll
    for (int i = 0; i < 4; i++) {
        rs_d[i] += __shfl_xor_sync(0xFFFFFFFFu, rs_d[i], 1);
        rs_d[i] += __shfl_xor_sync(0xFFFFFFFFu, rs_d[i], 2);
        rs_n[i] += __shfl_xor_sync(0xFFFFFFFFu, rs_n[i], 1);
        rs_n[i] += __shfl_xor_sync(0xFFFFFFFFu, rs_n[i], 2);
    }
    if ((lane & 3) == 0) {
        #pragma unroll
        for (int i = 0; i < 4; i++) {
            int rloc = wr * 32 + (i >> 1) * 16 + (i & 1) * 8 + rbase;
            rowD[wc * 256 + rloc] = rs_d[i];
            rowN[wc * 256 + rloc] = rs_n[i];
        }
    }
    __syncthreads();

    if (tid < 256) {
        g_pd[bj][row0 + tid] = rowD[tid] + rowD[256 + tid];
        g_pn[bj][row0 + tid] = rowN[tid] + rowN[256 + tid];
        if (!diag) {
            int c = tid >> 6, col = tid & 63;
            float sd = 0.f, sn = 0.f;
            #pragma unroll
            for (int s = 0; s < 8; s++) {
                sd += colD[c * 512 + s * 64 + col];
                sn += colN[c * 512 + s * 64 + col];
            }
            g_pd[bi][col0 + c * 64 + col] = sd;
            g_pn[bi][col0 + c * 64 + col] = sn;
        }
    }
    pdl_trigger();
}

// ---------------------------------------------------------------------------
// Finalize: counter-gated single kernel, PDL-overlapped ramp.
// ---------------------------------------------------------------------------
__global__ void snn_fin(float* __restrict__ out) {
    __shared__ float sred[256];
    pdl_wait();
    int i = blockIdx.x * 256 + threadIdx.x;
    float den = 0.f, num = 0.f;
    #pragma unroll
    for (int p = 0; p < NBLK; p++) { den += g_pd[p][i]; num += g_pn[p][i]; }
    float s = logf(den) - logf(num);
    sred[threadIdx.x] = s;
    __syncthreads();
    for (int off = 128; off > 0; off >>= 1) {
        if (threadIdx.x < off) sred[threadIdx.x] += sred[threadIdx.x + off];
        __syncthreads();
    }
    if (threadIdx.x == 0) {
        g_part[blockIdx.x] = sred[0];
        __threadfence();
        unsigned int old = atomicAdd(&g_cnt, 1u);
        if (old == 15u) {
            float tot = 0.f;
            #pragma unroll
            for (int b = 0; b < 16; b++) tot += g_part[b];
            out[0] = tot / (float)B;
        }
    }
}

// ---------------------------------------------------------------------------
extern "C" void kernel_launch(void* const* d_in, const int* in_sizes, int n_in,
                              void* d_out, int out_size) {
    const float* x = (const float*)d_in[0];
    const int*   y = (const int*)d_in[1];
    float* out = (float*)d_out;

    cudaFuncSetAttribute(snn_main, cudaFuncAttributeMaxDynamicSharedMemorySize, SMEM_SZ);

    snn_prep<<<B / 32, 256>>>(x, y);

    cudaLaunchAttribute attr[1];
    attr[0].id = cudaLaunchAttributeProgrammaticStreamSerialization;
    attr[0].val.programmaticStreamSerializationAllowed = 1;

    {
        cudaLaunchConfig_t cfg = {};
        cfg.gridDim = dim3(NTILES, 1, 1);
        cfg.blockDim = dim3(NT, 1, 1);
        cfg.dynamicSmemBytes = SMEM_SZ;
        cfg.attrs = attr;
        cfg.numAttrs = 1;
        cudaLaunchKernelEx(&cfg, snn_main);
    }
    {
        cudaLaunchConfig_t cfg = {};
        cfg.gridDim = dim3(16, 1, 1);
        cfg.blockDim = dim3(256, 1, 1);
        cfg.dynamicSmemBytes = 0;
        cfg.attrs = attr;
        cfg.numAttrs = 1;
        cudaLaunchKernelEx(&cfg, snn_fin, out);
    }
}